// round 15
// baseline (speedup 1.0000x reference)
#include <cuda_runtime.h>
#include <cuda_fp16.h>
#include <cstdint>
#include <math.h>

#define NN 4096
#define DD 64
#define LL 16
#define NT 32            // NN / 128 tiles per dim
#define NTRI 528         // NT*(NT+1)/2 triangular tile pairs
#define SURV_CAP (1 << 20)
#define GATE 52.0f       // fp16-noise-safe gate (true cutoff 50, exp(-25) mass)
#define SMS 72           // padded smem row stride (f16 elems): conflict-free ldmatrix

// ---------------- device scratch (static, no allocation) ----------------
__device__ __half g_xh[2][LL][NN][DD];           // packed f16 row-major
__device__ float  g_norm[2][LL][NN];             // squared norms (exact fp32)
__device__ float  g_r[2][LL][NN];                // row sums of K (init 1 = diag)
__device__ float  g_S[LL];                       // off-diag Sum Kx*Ky
__device__ double g_part[LL][4];                 // per-(l, quarter) finish partials
__device__ int    g_scount;

struct Surv { int ml; int i; int j; };
__device__ Surv g_surv[SURV_CAP];

// ---------------- warp MMA helpers (portable sm_80+ path) ----------------
__device__ __forceinline__ uint32_t smem_u32(const void* p) {
    uint32_t a;
    asm("{ .reg .u64 t; cvta.to.shared.u64 t, %1; cvt.u32.u64 %0, t; }"
        : "=r"(a) : "l"(p));
    return a;
}
__device__ __forceinline__ void ldsm_x4(uint32_t* r, uint32_t addr) {
    asm volatile("ldmatrix.sync.aligned.m8n8.x4.shared.b16 {%0,%1,%2,%3}, [%4];"
                 : "=r"(r[0]), "=r"(r[1]), "=r"(r[2]), "=r"(r[3]) : "r"(addr));
}
// f16 inputs, f16 accumulators (2 packed regs)
__device__ __forceinline__ void mma16816h(uint32_t* d, const uint32_t* a,
                                          uint32_t b0, uint32_t b1) {
    asm volatile("mma.sync.aligned.m16n8k16.row.col.f16.f16.f16.f16 "
                 "{%0,%1}, {%2,%3,%4,%5}, {%6,%7}, {%0,%1};"
                 : "+r"(d[0]), "+r"(d[1])
                 : "r"(a[0]), "r"(a[1]), "r"(a[2]), "r"(a[3]), "r"(b0), "r"(b1));
}

// ---------------- pack: (N, D, L) -> f16 row-major + norms + init fold -------
__global__ void pack_kernel(const float* __restrict__ X, const float* __restrict__ Y) {
    __shared__ float buf[DD * LL];      // buf[d*16 + l]
    const int m = blockIdx.y;
    const int i = blockIdx.x;
    const int t = threadIdx.x;
    const float* src = (m == 0 ? X : Y) + (size_t)i * (DD * LL);

#pragma unroll
    for (int q = 0; q < 4; ++q) buf[t + q * 256] = src[t + q * 256];

    // folded init (no dependence on buf; before the sync)
    if (m == 0 && i == 0) {
        if (t < LL) g_S[t] = 0.0f;
        if (t == 0) g_scount = 0;
    }
    __syncthreads();

#pragma unroll
    for (int q = 0; q < 4; ++q) {
        int e = t + q * 256;
        int l = e >> 6;
        int d = e & 63;
        g_xh[m][l][i][d] = __float2half_rn(buf[d * LL + l]);
    }
    if (t < LL) {
        float s = 0.0f;
#pragma unroll
        for (int d = 0; d < DD; ++d) { float v = buf[d * LL + t]; s = fmaf(v, v, s); }
        g_norm[m][t][i] = s;
        g_r[m][t][i] = 1.0f;            // row-sum init (diagonal term)
    }
}

// ---------------- main: 128x128x64 f16-accum HMMA Gram + masked epilogue -----
__global__ void __launch_bounds__(256, 2) gram_kernel() {
    // decode triangular tile pair (it <= jt)
    int p = blockIdx.x, it = 0, rem = NT;
    while (p >= rem) { p -= rem; rem--; it++; }
    const int jt = it + p;
    const int l = blockIdx.y;
    const int m = blockIdx.z;
    const int i0 = it * 128, j0 = jt * 128;

    __shared__ __align__(16) __half As[128 * SMS];
    __shared__ __align__(16) __half Bs[128 * SMS];
    __shared__ float nI[128], nJ[128];

    const int t = threadIdx.x;
    const int w = t >> 5;
    const int lane = t & 31;
    const int wm = w >> 2;            // 0..1  -> 64-row band
    const int wn = w & 3;             // 0..3  -> 32-col band
    const int qrow = lane >> 2;       // 0..7
    const int qc2 = (lane & 3) * 2;   // 0,2,4,6

    // fill smem tiles (row-major 64 -> padded 72)
    {
        const uint4* gA = (const uint4*)&g_xh[m][l][i0][0];   // 1024 chunks
        const uint4* gB = (const uint4*)&g_xh[m][l][j0][0];
#pragma unroll
        for (int q = 0; q < 4; ++q) {
            int idx = t + q * 256;
            int row = idx >> 3, c16 = idx & 7;
            *(uint4*)&As[row * SMS + c16 * 8] = gA[idx];
            *(uint4*)&Bs[row * SMS + c16 * 8] = gB[idx];
        }
        if (t < 128) nI[t] = g_norm[m][l][i0 + t];
        else         nJ[t - 128] = g_norm[m][l][j0 + t - 128];
    }
    __syncthreads();

    // diagonal tiles: warps whose whole sub-tile is strictly below the
    // diagonal can produce no survivors -> done.
    if (it == jt && wm == 1 && wn < 2) return;

    uint32_t acc[4][4][2];            // [m-frag][n8-frag][row-group], half2 packed
#pragma unroll
    for (int a = 0; a < 4; ++a)
#pragma unroll
        for (int b = 0; b < 4; ++b) { acc[a][b][0] = 0u; acc[a][b][1] = 0u; }

    const int lrow = lane & 15;       // ldmatrix row select
    const int lcol = (lane >> 4) * 8; // ldmatrix col select (elements)

    const uint32_t aBase = smem_u32(As);
    const uint32_t bBase = smem_u32(Bs);

#pragma unroll
    for (int ks = 0; ks < 4; ++ks) {
        const int kc = ks * 16;
        uint32_t af[4][4], bfr[2][4];
#pragma unroll
        for (int mf = 0; mf < 4; ++mf)
            ldsm_x4(af[mf], aBase + ((wm * 64 + mf * 16 + lrow) * SMS + kc + lcol) * 2);
#pragma unroll
        for (int nb = 0; nb < 2; ++nb)
            ldsm_x4(bfr[nb], bBase + ((wn * 32 + nb * 16 + lrow) * SMS + kc + lcol) * 2);
#pragma unroll
        for (int mf = 0; mf < 4; ++mf)
#pragma unroll
            for (int j = 0; j < 4; ++j) {
                const int nb = j >> 1, hi = j & 1;
                mma16816h(acc[mf][j], af[mf], bfr[nb][hi], bfr[nb][2 + hi]);
            }
    }

    // ---- epilogue: conservative per-fragment mask, exact path only if hit ----
    float rmin[4], cmin[4];
#pragma unroll
    for (int mf = 0; mf < 4; ++mf)
        rmin[mf] = 0.5f * fminf(nI[wm * 64 + mf * 16 + qrow],
                                nI[wm * 64 + mf * 16 + qrow + 8]);
#pragma unroll
    for (int j = 0; j < 4; ++j)
        cmin[j] = 0.5f * fminf(nJ[wn * 32 + j * 8 + qc2],
                               nJ[wn * 32 + j * 8 + qc2 + 1]);

    uint32_t mask = 0;
#pragma unroll
    for (int mf = 0; mf < 4; ++mf)
#pragma unroll
        for (int j = 0; j < 4; ++j) {
            __half2 h = __hmax2(*(__half2*)&acc[mf][j][0], *(__half2*)&acc[mf][j][1]);
            float mx = fmaxf(__low2float(h), __high2float(h));
            // mx > 0.5*(nImin+nJmin) - GATE/2  <=>  min possible d2 < GATE
            if (mx > rmin[mf] + cmin[j] - 0.5f * GATE) mask |= 1u << (mf * 4 + j);
        }

    if (mask) {   // cold path: exact per-element gate + survivor append
#pragma unroll
        for (int mf = 0; mf < 4; ++mf) {
#pragma unroll
            for (int j = 0; j < 4; ++j) {
                if (!(mask & (1u << (mf * 4 + j)))) continue;
#pragma unroll
                for (int r = 0; r < 4; ++r) {
                    const int li = wm * 64 + mf * 16 + qrow + ((r >> 1) << 3);
                    const int lj = wn * 32 + j * 8 + qc2 + (r & 1);
                    const int gi = i0 + li;
                    const int gj = j0 + lj;
                    __half2 h2 = *(__half2*)&acc[mf][j][r >> 1];
                    float dotv = (r & 1) ? __high2float(h2) : __low2float(h2);
                    float d2 = nI[li] + nJ[lj] - 2.0f * dotv;
                    if (gj > gi && d2 < GATE) {
                        int s = atomicAdd(&g_scount, 1);
                        if (s < SURV_CAP) {
                            g_surv[s].ml = (l << 1) | m;
                            g_surv[s].i = gi; g_surv[s].j = gj;
                        }
                    }
                }
            }
        }
    }
}

// ---------------- survivors: exact fp32 from ORIGINAL strided inputs ---------
// d2(i,j;l) = |xi|^2 + |xj|^2 - 2 * sum_d x[i,d,l]*x[j,d,l]  (stride-L reads)
__device__ __forceinline__ float dot_strided(const float* __restrict__ x,
                                             int i, int j, int l) {
    const float* a = x + (size_t)i * (DD * LL) + l;
    const float* b = x + (size_t)j * (DD * LL) + l;
    float s = 0.0f;
#pragma unroll
    for (int d = 0; d < DD; ++d)
        s = fmaf(__ldg(a + d * LL), __ldg(b + d * LL), s);
    return s;
}

__global__ void surv_kernel(const float* __restrict__ X, const float* __restrict__ Y) {
    int cnt = g_scount; if (cnt > SURV_CAP) cnt = SURV_CAP;
    for (int s = blockIdx.x * blockDim.x + threadIdx.x; s < cnt;
         s += gridDim.x * blockDim.x) {
        Surv v = g_surv[s];
        const int m = v.ml & 1;
        const int l = v.ml >> 1;
        const int om = m ^ 1;
        const float* xs = m == 0 ? X : Y;
        const float* xo = m == 0 ? Y : X;

        float d2s = g_norm[m][l][v.i] + g_norm[m][l][v.j]
                  - 2.0f * dot_strided(xs, v.i, v.j, l);
        d2s = fmaxf(d2s, 0.0f);
        float val = __expf(-0.5f * d2s);
        atomicAdd(&g_r[m][l][v.i], val);
        atomicAdd(&g_r[m][l][v.j], val);

        float d2o = g_norm[om][l][v.i] + g_norm[om][l][v.j]
                  - 2.0f * dot_strided(xo, v.i, v.j, l);
        d2o = fmaxf(d2o, 0.0f);
        if (m == 1 && d2o < GATE) continue;   // dedup: x-side owns double-gated pairs
        atomicAdd(&g_S[l], 2.0f * __expf(-0.5f * (d2s + d2o)));  // (i,j) and (j,i)
    }
}

// ---------------- finish stage 1: 4 blocks per timestep l --------------------
__global__ void finish_kernel() {
    __shared__ double sh0[256], sh1[256], sh2[256];
    const int t = threadIdx.x;
    const int l = blockIdx.x >> 2;
    const int qt = blockIdx.x & 3;
    const int base = qt * 1024;

    const float* rx = &g_r[0][l][0];
    const float* ry = &g_r[1][l][0];
    double p = 0.0, sx = 0.0, sy = 0.0;
    for (int i = base + t; i < base + 1024; i += 256) {
        double ax = (double)rx[i], ay = (double)ry[i];
        p += ax * ay; sx += ax; sy += ay;
    }
    sh0[t] = p; sh1[t] = sx; sh2[t] = sy;
    __syncthreads();
    for (int s = 128; s > 0; s >>= 1) {
        if (t < s) { sh0[t] += sh0[t + s]; sh1[t] += sh1[t + s]; sh2[t] += sh2[t + s]; }
        __syncthreads();
    }
    if (t == 0) {
        // pack 3 partials into g_part[l][qt] staging via 3 doubles in one slot?
        // keep it simple: store p, sx, sy in 3 interleaved arrays (reuse g_part
        // layout: [l][qt] holds p; sx/sy go in static arrays below)
        g_part[l][qt] = sh0[0];
    }
    // sx, sy partials
    __shared__ double unused;  (void)unused;
    if (t == 1) ((double*)&g_S)[0] = ((double*)&g_S)[0];  // no-op placeholder
    if (t == 0) {
        // store sx and sy in dedicated statics
        extern __device__ double g_psx[LL][4], g_psy[LL][4];
        g_psx[l][qt] = sh1[0];
        g_psy[l][qt] = sh2[0];
    }
}
__device__ double g_psx[LL][4], g_psy[LL][4];

// ---------------- finish stage 2: deterministic (l, q)-ordered combine -------
__global__ void final_kernel(float* __restrict__ out) {
    if (threadIdx.x == 0) {
        const double n = (double)NN;
        double total = 0.0;
        for (int l = 0; l < LL; ++l) {
            double p = 0.0, sx = 0.0, sy = 0.0;
            for (int q = 0; q < 4; ++q) {
                p += g_part[l][q]; sx += g_psx[l][q]; sy += g_psy[l][q];
            }
            double S = n + (double)g_S[l];               // diagonal contributes n
            double num = S - 2.0 * p / n + sx * sy / (n * n);
            total += num / ((n - 1.0) * (n - 1.0));
        }
        out[0] = (float)total;
    }
}

// ---------------- launch ----------------
extern "C" void kernel_launch(void* const* d_in, const int* in_sizes, int n_in,
                              void* d_out, int out_size) {
    const float* X = (const float*)d_in[0];
    const float* Y = (const float*)d_in[1];
    float* out = (float*)d_out;

    pack_kernel<<<dim3(NN, 2), 256>>>(X, Y);
    gram_kernel<<<dim3(NTRI, LL, 2), 256>>>();
    surv_kernel<<<512, 256>>>(X, Y);
    finish_kernel<<<LL * 4, 256>>>();
    final_kernel<<<1, 32>>>(out);
}

// round 16
// speedup vs baseline: 1.0693x; 1.0693x over previous
#include <cuda_runtime.h>
#include <cuda_fp16.h>
#include <cstdint>
#include <math.h>

#define NN 4096
#define DD 64
#define LL 16
#define NT 32            // NN / 128 tiles per dim
#define NTRI 528         // NT*(NT+1)/2 triangular tile pairs
#define SURV_CAP (1 << 20)
#define GATE 52.0f       // fp16-noise-safe gate (true cutoff 50, exp(-25) mass)
#define SMS 72           // padded smem row stride (f16 elems): conflict-free ldmatrix

// ---------------- device scratch (static, no allocation) ----------------
__device__ float  g_xp[2][LL][NN][DD];           // packed fp32 [mat][l][i][d]
__device__ __half g_xh[2][LL][NN][DD];           // packed f16 row-major
__device__ float  g_norm[2][LL][NN];             // squared norms (exact fp32)
__device__ float  g_r[2][LL][NN];                // row sums of K (init 1 = diag)
__device__ float  g_S[LL];                       // off-diag Sum Kx*Ky
__device__ double g_pp[LL][4];                   // finish partials: p
__device__ double g_psx[LL][4];                  // finish partials: sx
__device__ double g_psy[LL][4];                  // finish partials: sy
__device__ int    g_scount;

struct Surv { int ml; int i; int j; };
__device__ Surv g_surv[SURV_CAP];

// ---------------- warp MMA helpers (portable sm_80+ path) ----------------
__device__ __forceinline__ uint32_t smem_u32(const void* p) {
    uint32_t a;
    asm("{ .reg .u64 t; cvta.to.shared.u64 t, %1; cvt.u32.u64 %0, t; }"
        : "=r"(a) : "l"(p));
    return a;
}
__device__ __forceinline__ void ldsm_x4(uint32_t* r, uint32_t addr) {
    asm volatile("ldmatrix.sync.aligned.m8n8.x4.shared.b16 {%0,%1,%2,%3}, [%4];"
                 : "=r"(r[0]), "=r"(r[1]), "=r"(r[2]), "=r"(r[3]) : "r"(addr));
}
// f16 inputs, f16 accumulators (2 packed regs)
__device__ __forceinline__ void mma16816h(uint32_t* d, const uint32_t* a,
                                          uint32_t b0, uint32_t b1) {
    asm volatile("mma.sync.aligned.m16n8k16.row.col.f16.f16.f16.f16 "
                 "{%0,%1}, {%2,%3,%4,%5}, {%6,%7}, {%0,%1};"
                 : "+r"(d[0]), "+r"(d[1])
                 : "r"(a[0]), "r"(a[1]), "r"(a[2]), "r"(a[3]), "r"(b0), "r"(b1));
}

// ---------------- pack: (N, D, L) -> fp32 + f16 + norms + init fold ----------
__global__ void pack_kernel(const float* __restrict__ X, const float* __restrict__ Y) {
    __shared__ float buf[DD * LL];      // buf[d*16 + l]
    const int m = blockIdx.y;
    const int i = blockIdx.x;
    const int t = threadIdx.x;
    const float* src = (m == 0 ? X : Y) + (size_t)i * (DD * LL);

#pragma unroll
    for (int q = 0; q < 4; ++q) buf[t + q * 256] = src[t + q * 256];

    // folded init (no dependence on buf; before the sync)
    if (m == 0 && i == 0) {
        if (t < LL) g_S[t] = 0.0f;
        if (t == 0) g_scount = 0;
    }
    __syncthreads();

#pragma unroll
    for (int q = 0; q < 4; ++q) {
        int e = t + q * 256;
        int l = e >> 6;
        int d = e & 63;
        float v = buf[d * LL + l];
        g_xp[m][l][i][d] = v;
        g_xh[m][l][i][d] = __float2half_rn(v);
    }
    if (t < LL) {
        float s = 0.0f;
#pragma unroll
        for (int d = 0; d < DD; ++d) { float v = buf[d * LL + t]; s = fmaf(v, v, s); }
        g_norm[m][t][i] = s;
        g_r[m][t][i] = 1.0f;            // row-sum init (diagonal term)
    }
}

// ---------------- main: 128x128x64 f16-accum HMMA Gram + masked epilogue -----
__global__ void __launch_bounds__(256, 2) gram_kernel() {
    // decode triangular tile pair (it <= jt)
    int p = blockIdx.x, it = 0, rem = NT;
    while (p >= rem) { p -= rem; rem--; it++; }
    const int jt = it + p;
    const int l = blockIdx.y;
    const int m = blockIdx.z;
    const int i0 = it * 128, j0 = jt * 128;

    __shared__ __align__(16) __half As[128 * SMS];
    __shared__ __align__(16) __half Bs[128 * SMS];
    __shared__ float nI[128], nJ[128];

    const int t = threadIdx.x;
    const int w = t >> 5;
    const int lane = t & 31;
    const int wm = w >> 2;            // 0..1  -> 64-row band
    const int wn = w & 3;             // 0..3  -> 32-col band
    const int qrow = lane >> 2;       // 0..7
    const int qc2 = (lane & 3) * 2;   // 0,2,4,6

    // fill smem tiles (row-major 64 -> padded 72)
    {
        const uint4* gA = (const uint4*)&g_xh[m][l][i0][0];   // 1024 chunks
        const uint4* gB = (const uint4*)&g_xh[m][l][j0][0];
#pragma unroll
        for (int q = 0; q < 4; ++q) {
            int idx = t + q * 256;
            int row = idx >> 3, c16 = idx & 7;
            *(uint4*)&As[row * SMS + c16 * 8] = gA[idx];
            *(uint4*)&Bs[row * SMS + c16 * 8] = gB[idx];
        }
        if (t < 128) nI[t] = g_norm[m][l][i0 + t];
        else         nJ[t - 128] = g_norm[m][l][j0 + t - 128];
    }
    __syncthreads();

    // diagonal tiles: warps whose whole sub-tile is strictly below the
    // diagonal can produce no survivors -> done.
    if (it == jt && wm == 1 && wn < 2) return;

    uint32_t acc[4][4][2];            // [m-frag][n8-frag][row-group], half2 packed
#pragma unroll
    for (int a = 0; a < 4; ++a)
#pragma unroll
        for (int b = 0; b < 4; ++b) { acc[a][b][0] = 0u; acc[a][b][1] = 0u; }

    const int lrow = lane & 15;       // ldmatrix row select
    const int lcol = (lane >> 4) * 8; // ldmatrix col select (elements)

    const uint32_t aBase = smem_u32(As);
    const uint32_t bBase = smem_u32(Bs);

#pragma unroll
    for (int ks = 0; ks < 4; ++ks) {
        const int kc = ks * 16;
        uint32_t af[4][4], bfr[2][4];
#pragma unroll
        for (int mf = 0; mf < 4; ++mf)
            ldsm_x4(af[mf], aBase + ((wm * 64 + mf * 16 + lrow) * SMS + kc + lcol) * 2);
#pragma unroll
        for (int nb = 0; nb < 2; ++nb)
            ldsm_x4(bfr[nb], bBase + ((wn * 32 + nb * 16 + lrow) * SMS + kc + lcol) * 2);
#pragma unroll
        for (int mf = 0; mf < 4; ++mf)
#pragma unroll
            for (int j = 0; j < 4; ++j) {
                const int nb = j >> 1, hi = j & 1;
                mma16816h(acc[mf][j], af[mf], bfr[nb][hi], bfr[nb][2 + hi]);
            }
    }

    // ---- epilogue: conservative per-fragment mask, exact path only if hit ----
    float rmin[4], cmin[4];
#pragma unroll
    for (int mf = 0; mf < 4; ++mf)
        rmin[mf] = 0.5f * fminf(nI[wm * 64 + mf * 16 + qrow],
                                nI[wm * 64 + mf * 16 + qrow + 8]);
#pragma unroll
    for (int j = 0; j < 4; ++j)
        cmin[j] = 0.5f * fminf(nJ[wn * 32 + j * 8 + qc2],
                               nJ[wn * 32 + j * 8 + qc2 + 1]);

    uint32_t mask = 0;
#pragma unroll
    for (int mf = 0; mf < 4; ++mf)
#pragma unroll
        for (int j = 0; j < 4; ++j) {
            __half2 h = __hmax2(*(__half2*)&acc[mf][j][0], *(__half2*)&acc[mf][j][1]);
            float mx = fmaxf(__low2float(h), __high2float(h));
            // mx > 0.5*(nImin+nJmin) - GATE/2  <=>  min possible d2 < GATE
            if (mx > rmin[mf] + cmin[j] - 0.5f * GATE) mask |= 1u << (mf * 4 + j);
        }

    if (mask) {   // cold path: exact per-element gate + survivor append
#pragma unroll
        for (int mf = 0; mf < 4; ++mf) {
#pragma unroll
            for (int j = 0; j < 4; ++j) {
                if (!(mask & (1u << (mf * 4 + j)))) continue;
#pragma unroll
                for (int r = 0; r < 4; ++r) {
                    const int li = wm * 64 + mf * 16 + qrow + ((r >> 1) << 3);
                    const int lj = wn * 32 + j * 8 + qc2 + (r & 1);
                    const int gi = i0 + li;
                    const int gj = j0 + lj;
                    __half2 h2 = *(__half2*)&acc[mf][j][r >> 1];
                    float dotv = (r & 1) ? __high2float(h2) : __low2float(h2);
                    float d2 = nI[li] + nJ[lj] - 2.0f * dotv;
                    if (gj > gi && d2 < GATE) {
                        int s = atomicAdd(&g_scount, 1);
                        if (s < SURV_CAP) {
                            g_surv[s].ml = (l << 1) | m;
                            g_surv[s].i = gi; g_surv[s].j = gj;
                        }
                    }
                }
            }
        }
    }
}

// ---------------- survivors: exact fp32 recompute + row sums + S -------------
__device__ __forceinline__ float dot64(const float* __restrict__ a, const float* __restrict__ b) {
    float s = 0.0f;
#pragma unroll
    for (int q = 0; q < 16; ++q) {
        float4 x = ((const float4*)a)[q];
        float4 y = ((const float4*)b)[q];
        s = fmaf(x.x, y.x, s); s = fmaf(x.y, y.y, s);
        s = fmaf(x.z, y.z, s); s = fmaf(x.w, y.w, s);
    }
    return s;
}

__global__ void surv_kernel() {
    int cnt = g_scount; if (cnt > SURV_CAP) cnt = SURV_CAP;
    for (int s = blockIdx.x * blockDim.x + threadIdx.x; s < cnt;
         s += gridDim.x * blockDim.x) {
        Surv v = g_surv[s];
        const int m = v.ml & 1;
        const int l = v.ml >> 1;
        const int om = m ^ 1;

        const float* bs = &g_xp[m][l][0][0];
        float d2s = g_norm[m][l][v.i] + g_norm[m][l][v.j]
                  - 2.0f * dot64(bs + (size_t)v.i * DD, bs + (size_t)v.j * DD);
        d2s = fmaxf(d2s, 0.0f);
        float val = __expf(-0.5f * d2s);
        atomicAdd(&g_r[m][l][v.i], val);
        atomicAdd(&g_r[m][l][v.j], val);

        const float* bo = &g_xp[om][l][0][0];
        float d2o = g_norm[om][l][v.i] + g_norm[om][l][v.j]
                  - 2.0f * dot64(bo + (size_t)v.i * DD, bo + (size_t)v.j * DD);
        d2o = fmaxf(d2o, 0.0f);
        if (m == 1 && d2o < GATE) continue;   // dedup: x-side owns double-gated pairs
        atomicAdd(&g_S[l], 2.0f * __expf(-0.5f * (d2s + d2o)));  // (i,j) and (j,i)
    }
}

// ---------------- finish stage 1: 4 blocks per timestep l --------------------
__global__ void finish_kernel() {
    __shared__ double sh0[256], sh1[256], sh2[256];
    const int t = threadIdx.x;
    const int l = blockIdx.x >> 2;
    const int qt = blockIdx.x & 3;
    const int base = qt * 1024;

    const float* rx = &g_r[0][l][0];
    const float* ry = &g_r[1][l][0];
    double p = 0.0, sx = 0.0, sy = 0.0;
    for (int i = base + t; i < base + 1024; i += 256) {
        double ax = (double)rx[i], ay = (double)ry[i];
        p += ax * ay; sx += ax; sy += ay;
    }
    sh0[t] = p; sh1[t] = sx; sh2[t] = sy;
    __syncthreads();
    for (int s = 128; s > 0; s >>= 1) {
        if (t < s) { sh0[t] += sh0[t + s]; sh1[t] += sh1[t + s]; sh2[t] += sh2[t + s]; }
        __syncthreads();
    }
    if (t == 0) {
        g_pp[l][qt] = sh0[0];
        g_psx[l][qt] = sh1[0];
        g_psy[l][qt] = sh2[0];
    }
}

// ---------------- finish stage 2: deterministic (l, q)-ordered combine -------
__global__ void final_kernel(float* __restrict__ out) {
    if (threadIdx.x == 0) {
        const double n = (double)NN;
        double total = 0.0;
        for (int l = 0; l < LL; ++l) {
            double p = 0.0, sx = 0.0, sy = 0.0;
            for (int q = 0; q < 4; ++q) {
                p += g_pp[l][q]; sx += g_psx[l][q]; sy += g_psy[l][q];
            }
            double S = n + (double)g_S[l];               // diagonal contributes n
            double num = S - 2.0 * p / n + sx * sy / (n * n);
            total += num / ((n - 1.0) * (n - 1.0));
        }
        out[0] = (float)total;
    }
}

// ---------------- launch ----------------
extern "C" void kernel_launch(void* const* d_in, const int* in_sizes, int n_in,
                              void* d_out, int out_size) {
    const float* X = (const float*)d_in[0];
    const float* Y = (const float*)d_in[1];
    float* out = (float*)d_out;

    pack_kernel<<<dim3(NN, 2), 256>>>(X, Y);
    gram_kernel<<<dim3(NTRI, LL, 2), 256>>>();
    surv_kernel<<<512, 256>>>();
    finish_kernel<<<LL * 4, 256>>>();
    final_kernel<<<1, 32>>>(out);
}